// round 11
// baseline (speedup 1.0000x reference)
#include <cuda_runtime.h>
#include <cuda_bf16.h>
#include <math.h>

// Problem dims
#define BB 16
#define SS 100
#define LL 100          // MAX_CODE_LEN
#define FEAT 20         // INPUT_DIM
#define EMB 100
#define DD 320          // D = 20 + 3*100
#define RNNIN 340       // 2*20 + 3*100
#define HID 128
#define G4 512
#define NOUT 10

#define NVOC_N 10002
#define NVOC_P 50002
#define PROJ_NODE_BLOCKS 79   // ceil(10002/128)
#define PROJ_PATH_BLOCKS 391  // ceil(50002/128)
#define WS_STRIDE 68          // multiple of 4: float4 stays 16B-aligned
#define AS_STRIDE 104         // multiple of 4

// -------- scratch (device globals; no allocation allowed) --------
static __device__ float g_Tn[NVOC_N * 640];    // [v][0:320]=start proj, [v][320:640]=end proj
static __device__ float g_Tp[NVOC_P * 320];    // path proj
static __device__ float g_cw[BB*LL*SS];        // [b][l][s]
static __device__ float g_aw[BB*SS*LL];        // [b][s][l]
static __device__ float g_rnn[BB*SS*RNNIN];    // [b][s][340]
static __device__ float g_gx[BB*SS*G4];        // x-part gates
static __device__ float g_hs[BB*SS*HID];       // lstm outputs
static __device__ float g_WihT[RNNIN*G4];      // [k][n] coalesced
static __device__ float4 g_Whh4[HID*HID];      // [k][n] -> gates (i,f,g,o) packed

__device__ __forceinline__ float sigf(float x) { return 1.0f / (1.0f + expf(-x)); }
__device__ __forceinline__ float tanh_fast(float x) {
    float y;
    asm("tanh.approx.f32 %0, %1;" : "=f"(y) : "f"(x));
    return y;
}

// ----------------------------------------------------------------
// K0: transpose W_ih; pack W_hh by gate quadruple
// ----------------------------------------------------------------
__global__ void k0_transpose(const float* __restrict__ Wih, const float* __restrict__ Whh) {
    int t = blockIdx.x * blockDim.x + threadIdx.x;
    if (t < RNNIN * G4) {          // Wih is [512][340]
        int n = t / RNNIN, k = t % RNNIN;
        g_WihT[k * G4 + n] = Wih[t];
    }
    if (t < HID * HID) {           // Whh is [512][128]: rows g*128+n, cols k
        int k = t / HID, n = t % HID;
        g_Whh4[k * HID + n] = make_float4(
            Whh[(0 * HID + n) * HID + k],
            Whh[(1 * HID + n) * HID + k],
            Whh[(2 * HID + n) * HID + k],
            Whh[(3 * HID + n) * HID + k]);
    }
}

// ----------------------------------------------------------------
// KP: project embedding tables through W_trans column blocks.
// ----------------------------------------------------------------
__global__ void __launch_bounds__(256, 1)
kp_project(const float* __restrict__ etab_n,
           const float* __restrict__ etab_p,
           const float* __restrict__ Wt)
{
    extern __shared__ float sm[];
    float* A_s = sm;                        // 128 * 104
    float* W_s = sm + 128 * AS_STRIDE;      // 100 * 68

    const int t = threadIdx.x;
    const bool isnode = blockIdx.x < PROJ_NODE_BLOCKS;
    const int vb = isnode ? blockIdx.x : blockIdx.x - PROJ_NODE_BLOCKS;
    const int v0 = vb * 128;
    const int nv = isnode ? NVOC_N : NVOC_P;
    const float* tab = isnode ? etab_n : etab_p;
    float* outp = isnode ? g_Tn : g_Tp;
    const int ostride = isnode ? 640 : 320;
    const int ndb = isnode ? 10 : 5;

    for (int e = t; e < 128 * EMB; e += 256) {
        int r = e / EMB, k = e % EMB;
        float v = 0.f;
        if (v0 + r < nv) v = tab[(v0 + r) * EMB + k];
        A_s[r * AS_STRIDE + k] = v;
    }

    const int tx = t & 15;
    const int ty = t >> 4;
    const int d0 = tx * 4;
    const int r0 = ty * 8;

    for (int db = 0; db < ndb; db++) {
        const int dbase = db * 64;
        int wrow, kofs;
        if (isnode) {
            if (db < 5) { wrow = dbase;       kofs = 0;   }
            else        { wrow = dbase - 320; kofs = 100; }
        } else          { wrow = dbase;       kofs = 200; }

        __syncthreads();
        for (int e = t; e < 64 * EMB; e += 256) {
            int d = e / EMB, k = e % EMB;
            W_s[k * WS_STRIDE + d] = Wt[(wrow + d) * DD + kofs + k];
        }
        __syncthreads();

        float acc[8][4];
#pragma unroll
        for (int i = 0; i < 8; i++)
#pragma unroll
            for (int j = 0; j < 4; j++) acc[i][j] = 0.f;

#pragma unroll 2
        for (int k = 0; k < EMB; k += 4) {
            float4 wv0 = *(const float4*)&W_s[(k + 0) * WS_STRIDE + d0];
            float4 wv1 = *(const float4*)&W_s[(k + 1) * WS_STRIDE + d0];
            float4 wv2 = *(const float4*)&W_s[(k + 2) * WS_STRIDE + d0];
            float4 wv3 = *(const float4*)&W_s[(k + 3) * WS_STRIDE + d0];
#pragma unroll
            for (int i = 0; i < 8; i++) {
                float4 a = *(const float4*)&A_s[(r0 + i) * AS_STRIDE + k];
                acc[i][0] += a.x * wv0.x + a.y * wv1.x + a.z * wv2.x + a.w * wv3.x;
                acc[i][1] += a.x * wv0.y + a.y * wv1.y + a.z * wv2.y + a.w * wv3.y;
                acc[i][2] += a.x * wv0.z + a.y * wv1.z + a.z * wv2.z + a.w * wv3.z;
                acc[i][3] += a.x * wv0.w + a.y * wv1.w + a.z * wv2.w + a.w * wv3.w;
            }
        }
#pragma unroll
        for (int i = 0; i < 8; i++) {
            int r = v0 + r0 + i;
            if (r < nv) {
                float4 o = make_float4(acc[i][0], acc[i][1], acc[i][2], acc[i][3]);
                *(float4*)&outp[r * ostride + dbase + d0] = o;
            }
        }
    }
}

// ----------------------------------------------------------------
// K1b: per (b,s): f_proj = feat @ Wt4^T + bt; per context l:
//   cw = ba + sum_d Wa[d]*tanh(Tn_s[si][d]+Tn_e[ei][d]+Tp[pi][d]+fproj[d])
// Each warp handles TWO contexts (l, l+50) for doubled gather MLP.
// ----------------------------------------------------------------
__global__ void __launch_bounds__(256)
k1b_cw(const float* __restrict__ x,
       const float* __restrict__ Wt,
       const float* __restrict__ bt,
       const float* __restrict__ Wa,
       const float* __restrict__ ba)
{
    __shared__ int si[LL], pi[LL], ei[LL];
    __shared__ float4 fproj4[DD/4], was4[DD/4];
    __shared__ float feat_s[FEAT];
    float* fproj = (float*)fproj4;
    float* was   = (float*)was4;

    const int bs = blockIdx.x;
    const int b = bs / SS, s = bs % SS;
    const int t = threadIdx.x;

    if (t < LL) {
        int xb = bs * DD + FEAT + 3 * t;
        si[t] = (int)x[xb];
        pi[t] = (int)x[xb + 1];
        ei[t] = (int)x[xb + 2];
    }
    if (t < FEAT) feat_s[t] = x[bs * DD + t];
    __syncthreads();

    for (int d = t; d < DD; d += 256) {
        float acc = bt[d];
        const float* wrow = &Wt[d * DD + 300];
#pragma unroll
        for (int k = 0; k < FEAT; k++) acc += feat_s[k] * wrow[k];
        fproj[d] = acc;
        was[d] = Wa[d];
    }
    __syncthreads();

    const int warp = t >> 5, lane = t & 31;
    const float bav = ba[0];
    // two contexts per warp: l0 in [0,50), l1 = l0+50
    for (int l0 = warp; l0 < 50; l0 += 8) {
        const int l1 = l0 + 50;
        const float4* pn0 = (const float4*)&g_Tn[si[l0] * 640];
        const float4* pe0 = (const float4*)&g_Tn[ei[l0] * 640 + 320];
        const float4* pp0 = (const float4*)&g_Tp[pi[l0] * 320];
        const float4* pn1 = (const float4*)&g_Tn[si[l1] * 640];
        const float4* pe1 = (const float4*)&g_Tn[ei[l1] * 640 + 320];
        const float4* pp1 = (const float4*)&g_Tp[pi[l1] * 320];
        float sum0 = 0.f, sum1 = 0.f;
        for (int j = lane; j < DD/4; j += 32) {
            float4 f = fproj4[j], w = was4[j];
            float4 a0 = pn0[j], b0 = pe0[j], c0 = pp0[j];
            float4 a1 = pn1[j], b1 = pe1[j], c1 = pp1[j];
            sum0 += w.x * tanh_fast(a0.x + b0.x + c0.x + f.x)
                  + w.y * tanh_fast(a0.y + b0.y + c0.y + f.y)
                  + w.z * tanh_fast(a0.z + b0.z + c0.z + f.z)
                  + w.w * tanh_fast(a0.w + b0.w + c0.w + f.w);
            sum1 += w.x * tanh_fast(a1.x + b1.x + c1.x + f.x)
                  + w.y * tanh_fast(a1.y + b1.y + c1.y + f.y)
                  + w.z * tanh_fast(a1.z + b1.z + c1.z + f.z)
                  + w.w * tanh_fast(a1.w + b1.w + c1.w + f.w);
        }
#pragma unroll
        for (int off = 16; off; off >>= 1) {
            sum0 += __shfl_xor_sync(~0u, sum0, off);
            sum1 += __shfl_xor_sync(~0u, sum1, off);
        }
        if (lane == 0) {
            g_cw[(b * LL + l0) * SS + s] = sum0 + bav;
            g_cw[(b * LL + l1) * SS + s] = sum1 + bav;
        }
    }
}

// ----------------------------------------------------------------
// K2: softmax over s (axis=1) for each (b,l); write aw in [b][s][l]
// ----------------------------------------------------------------
__global__ void k2_softmax() {
    const int bl = blockIdx.x;
    const int t  = threadIdx.x;    // 128
    const float* row = g_cw + bl * SS;
    float v0 = (t < SS) ? row[t] : -3.0e38f;

    __shared__ float sw[4];
    float v = v0;
#pragma unroll
    for (int off = 16; off; off >>= 1) v = fmaxf(v, __shfl_xor_sync(~0u, v, off));
    if ((t & 31) == 0) sw[t >> 5] = v;
    __syncthreads();
    float mx = fmaxf(fmaxf(sw[0], sw[1]), fmaxf(sw[2], sw[3]));
    __syncthreads();

    float e = (t < SS) ? expf(v0 - mx) : 0.f;
    float sv = e;
#pragma unroll
    for (int off = 16; off; off >>= 1) sv += __shfl_xor_sync(~0u, sv, off);
    if ((t & 31) == 0) sw[t >> 5] = sv;
    __syncthreads();
    float tot = sw[0] + sw[1] + sw[2] + sw[3];

    if (t < SS) {
        int b = bl / LL, l = bl % LL;
        g_aw[(b * SS + t) * LL + l] = e / tot;
    }
}

// ----------------------------------------------------------------
// K5 core (shared by probe and real kernel)
// ----------------------------------------------------------------
__device__ __forceinline__ void lstm_run(int b, int nsteps)
{
    __shared__ float h_s[HID];
    __shared__ float4 red[4][HID];
    const int n = threadIdx.x & 127;
    const int q = threadIdx.x >> 7;

    if (threadIdx.x < HID) h_s[threadIdx.x] = 0.f;
    float c = 0.f;
    __syncthreads();

    const float4* wbase = &g_Whh4[q * 32 * HID + n];
    const float*  hq    = &h_s[q * 32];

    for (int s = 0; s < nsteps; s++) {
        float4 acc = make_float4(0.f, 0.f, 0.f, 0.f);
#pragma unroll 8
        for (int kk = 0; kk < 32; kk++) {
            float4 w = wbase[kk * HID];
            float hk = hq[kk];
            acc.x += w.x * hk;
            acc.y += w.y * hk;
            acc.z += w.z * hk;
            acc.w += w.w * hk;
        }
        red[q][n] = acc;
        __syncthreads();
        if (threadIdx.x < HID) {
            float4 a0 = red[0][threadIdx.x];
            float4 a1 = red[1][threadIdx.x];
            float4 a2 = red[2][threadIdx.x];
            float4 a3 = red[3][threadIdx.x];
            const float* gx = &g_gx[(b * SS + s) * G4];
            float gi = a0.x + a1.x + a2.x + a3.x + gx[threadIdx.x];
            float gf = a0.y + a1.y + a2.y + a3.y + gx[HID + threadIdx.x];
            float gg = a0.z + a1.z + a2.z + a3.z + gx[2 * HID + threadIdx.x];
            float go = a0.w + a1.w + a2.w + a3.w + gx[3 * HID + threadIdx.x];
            c = sigf(gf) * c + sigf(gi) * tanhf(gg);
            float h = sigf(go) * tanhf(c);
            h_s[threadIdx.x] = h;
            g_hs[(b * SS + s) * HID + threadIdx.x] = h;
        }
        __syncthreads();
    }
}

// Probe: 10 steps, result later overwritten by real k5 (profiling only).
__global__ void __launch_bounds__(512)
k5_probe() { lstm_run(blockIdx.x, 10); }

__global__ void __launch_bounds__(512)
k5_lstm() { lstm_run(blockIdx.x, SS); }

// ----------------------------------------------------------------
// K3: code_vec via re-gather; rnn_in = [feat(20), code_vec(320)]
// ----------------------------------------------------------------
__global__ void k3_codevec(const float* __restrict__ x,
                           const float* __restrict__ etab_n,
                           const float* __restrict__ etab_p)
{
    __shared__ float aw_s[LL];
    __shared__ int si[LL], pi[LL], ei[LL];
    __shared__ float awsum_s;
    const int bs = blockIdx.x;
    const int t  = threadIdx.x;   // 128

    if (t < LL) {
        aw_s[t] = g_aw[bs * LL + t];
        int xb = bs * DD + FEAT + 3 * t;
        si[t] = (int)x[xb];
        pi[t] = (int)x[xb + 1];
        ei[t] = (int)x[xb + 2];
    }
    __syncthreads();
    if (t == 0) {
        float a = 0.f;
        for (int l = 0; l < LL; l++) a += aw_s[l];
        awsum_s = a;
    }
    __syncthreads();

    float* outrow = g_rnn + bs * RNNIN;
    for (int j = t; j < RNNIN; j += 128) {
        float v;
        if (j < FEAT) {
            v = x[bs * DD + j];
        } else {
            int k = j - FEAT;
            float acc = 0.f;
            if (k < EMB) {
                for (int l = 0; l < LL; l++) acc += etab_n[si[l] * EMB + k] * aw_s[l];
            } else if (k < 2 * EMB) {
                int km = k - EMB;
                for (int l = 0; l < LL; l++) acc += etab_n[ei[l] * EMB + km] * aw_s[l];
            } else if (k < 3 * EMB) {
                int km = k - 2 * EMB;
                for (int l = 0; l < LL; l++) acc += etab_p[pi[l] * EMB + km] * aw_s[l];
            } else {
                acc = x[bs * DD + (k - 3 * EMB)] * awsum_s;
            }
            v = acc;
        }
        outrow[j] = v;
    }
}

// ----------------------------------------------------------------
// K4: g_gx = rnn_in @ W_ih^T + b_ih + b_hh  (coalesced WihT scalar loads)
// ----------------------------------------------------------------
__global__ void __launch_bounds__(512)
k4_gates(const float* __restrict__ bih, const float* __restrict__ bhh)
{
    __shared__ float A_s[16 * RNNIN];
    const int n  = threadIdx.x;
    const int r0 = blockIdx.x * 16;

    for (int e = n; e < 16 * RNNIN; e += 512)
        A_s[e] = g_rnn[r0 * RNNIN + e];
    __syncthreads();

    float acc[16];
#pragma unroll
    for (int i = 0; i < 16; i++) acc[i] = 0.f;

#pragma unroll 2
    for (int k = 0; k < RNNIN; k += 4) {
        float w0 = g_WihT[(k + 0) * G4 + n];
        float w1 = g_WihT[(k + 1) * G4 + n];
        float w2 = g_WihT[(k + 2) * G4 + n];
        float w3 = g_WihT[(k + 3) * G4 + n];
#pragma unroll
        for (int i = 0; i < 16; i++) {
            float4 a = *(const float4*)&A_s[i * RNNIN + k];
            acc[i] += a.x * w0 + a.y * w1 + a.z * w2 + a.w * w3;
        }
    }
    float bias = bih[n] + bhh[n];
#pragma unroll
    for (int i = 0; i < 16; i++)
        g_gx[(r0 + i) * G4 + n] = acc[i] + bias;
}

// ----------------------------------------------------------------
// K6: out = sigmoid(hs @ W_fc^T + b_fc)
// ----------------------------------------------------------------
__global__ void k6_fc(const float* __restrict__ Wfc,
                      const float* __restrict__ bfc,
                      float* __restrict__ out)
{
    int t = blockIdx.x * blockDim.x + threadIdx.x;
    if (t >= BB * SS * NOUT) return;
    int bs = t / NOUT;
    int o  = t % NOUT;
    const float* hrow = g_hs + bs * HID;
    const float* wrow = Wfc + o * HID;
    float acc = bfc[o];
#pragma unroll 8
    for (int u = 0; u < HID; u++) acc += hrow[u] * wrow[u];
    out[t] = sigf(acc);
}

// ----------------------------------------------------------------
extern "C" void kernel_launch(void* const* d_in, const int* in_sizes, int n_in,
                              void* d_out, int out_size)
{
    const float* x      = (const float*)d_in[0];
    const float* etab_n = (const float*)d_in[1];
    const float* etab_p = (const float*)d_in[2];
    const float* Wt     = (const float*)d_in[3];
    const float* bt     = (const float*)d_in[4];
    const float* Wa     = (const float*)d_in[5];
    const float* ba     = (const float*)d_in[6];
    const float* Wih    = (const float*)d_in[7];
    const float* Whh    = (const float*)d_in[8];
    const float* bih    = (const float*)d_in[9];
    const float* bhh    = (const float*)d_in[10];
    const float* Wfc    = (const float*)d_in[11];
    const float* bfc    = (const float*)d_in[12];
    float* out = (float*)d_out;

    const int kp_smem = (128 * AS_STRIDE + 100 * WS_STRIDE) * 4;
    cudaFuncSetAttribute(kp_project, cudaFuncAttributeMaxDynamicSharedMemorySize, kp_smem);

    {
        int total = RNNIN * G4;
        k0_transpose<<<(total + 255) / 256, 256>>>(Wih, Whh);     // 1
    }
    kp_project<<<PROJ_NODE_BLOCKS + PROJ_PATH_BLOCKS, 256, kp_smem>>>(etab_n, etab_p, Wt); // 2
    k1b_cw<<<BB * SS, 256>>>(x, Wt, bt, Wa, ba);                  // 3
    k5_probe<<<BB, 512>>>();                                      // 4 <- ncu capture slot (profiling only)
    k2_softmax<<<BB * LL, 128>>>();                               // 5
    k3_codevec<<<BB * SS, 128>>>(x, etab_n, etab_p);              // 6
    k4_gates<<<BB * SS / 16, 512>>>(bih, bhh);                    // 7
    k5_lstm<<<BB, 512>>>();                                       // 8
    {
        int total = BB * SS * NOUT;
        k6_fc<<<(total + 255) / 256, 256>>>(Wfc, bfc, out);       // 9
    }
}

// round 13
// speedup vs baseline: 1.2091x; 1.2091x over previous
#include <cuda_runtime.h>
#include <cuda_bf16.h>
#include <math.h>

// Problem dims
#define BB 16
#define SS 100
#define LL 100          // MAX_CODE_LEN
#define FEAT 20         // INPUT_DIM
#define EMB 100
#define DD 320          // D = 20 + 3*100
#define RNNIN 340       // 2*20 + 3*100
#define HID 128
#define G4 512
#define NOUT 10

#define NVOC_N 10002
#define NVOC_P 50002
#define PROJ_NODE_BLOCKS 79   // ceil(10002/128)
#define PROJ_PATH_BLOCKS 391  // ceil(50002/128)
#define WS_STRIDE 68          // multiple of 4: float4 stays 16B-aligned
#define AS_STRIDE 104         // multiple of 4

#define KSM 104               // k-slices of W_hh resident in smem (of 128)

// -------- scratch (device globals; no allocation allowed) --------
static __device__ float g_Tn[NVOC_N * 640];    // [v][0:320]=start proj, [v][320:640]=end proj
static __device__ float g_Tp[NVOC_P * 320];    // path proj
static __device__ float g_cw[BB*LL*SS];        // [b][l][s]
static __device__ float g_aw[BB*SS*LL];        // [b][s][l]
static __device__ float g_rnn[BB*SS*RNNIN];    // [b][s][340]
static __device__ float g_gx[BB*SS*G4];        // x-part gates
static __device__ float g_hs[BB*SS*HID];       // lstm outputs
static __device__ float g_WihT[RNNIN*G4];      // [k][n] coalesced
static __device__ float4 g_Whh4[HID*HID];      // [k][n] -> gates (i,f,g,o) packed

__device__ __forceinline__ float sigf(float x) { return 1.0f / (1.0f + expf(-x)); }
__device__ __forceinline__ float tanh_fast(float x) {
    float y;
    asm("tanh.approx.f32 %0, %1;" : "=f"(y) : "f"(x));
    return y;
}

// ----------------------------------------------------------------
// K0: transpose W_ih; pack W_hh by gate quadruple
// ----------------------------------------------------------------
__global__ void k0_transpose(const float* __restrict__ Wih, const float* __restrict__ Whh) {
    int t = blockIdx.x * blockDim.x + threadIdx.x;
    if (t < RNNIN * G4) {          // Wih is [512][340]
        int n = t / RNNIN, k = t % RNNIN;
        g_WihT[k * G4 + n] = Wih[t];
    }
    if (t < HID * HID) {           // Whh is [512][128]: rows g*128+n, cols k
        int k = t / HID, n = t % HID;
        g_Whh4[k * HID + n] = make_float4(
            Whh[(0 * HID + n) * HID + k],
            Whh[(1 * HID + n) * HID + k],
            Whh[(2 * HID + n) * HID + k],
            Whh[(3 * HID + n) * HID + k]);
    }
}

// ----------------------------------------------------------------
// KP: project embedding tables through W_trans column blocks.
// ----------------------------------------------------------------
__global__ void __launch_bounds__(256, 1)
kp_project(const float* __restrict__ etab_n,
           const float* __restrict__ etab_p,
           const float* __restrict__ Wt)
{
    extern __shared__ float sm[];
    float* A_s = sm;                        // 128 * 104
    float* W_s = sm + 128 * AS_STRIDE;      // 100 * 68

    const int t = threadIdx.x;
    const bool isnode = blockIdx.x < PROJ_NODE_BLOCKS;
    const int vb = isnode ? blockIdx.x : blockIdx.x - PROJ_NODE_BLOCKS;
    const int v0 = vb * 128;
    const int nv = isnode ? NVOC_N : NVOC_P;
    const float* tab = isnode ? etab_n : etab_p;
    float* outp = isnode ? g_Tn : g_Tp;
    const int ostride = isnode ? 640 : 320;
    const int ndb = isnode ? 10 : 5;

    for (int e = t; e < 128 * EMB; e += 256) {
        int r = e / EMB, k = e % EMB;
        float v = 0.f;
        if (v0 + r < nv) v = tab[(v0 + r) * EMB + k];
        A_s[r * AS_STRIDE + k] = v;
    }

    const int tx = t & 15;
    const int ty = t >> 4;
    const int d0 = tx * 4;
    const int r0 = ty * 8;

    for (int db = 0; db < ndb; db++) {
        const int dbase = db * 64;
        int wrow, kofs;
        if (isnode) {
            if (db < 5) { wrow = dbase;       kofs = 0;   }
            else        { wrow = dbase - 320; kofs = 100; }
        } else          { wrow = dbase;       kofs = 200; }

        __syncthreads();
        for (int e = t; e < 64 * EMB; e += 256) {
            int d = e / EMB, k = e % EMB;
            W_s[k * WS_STRIDE + d] = Wt[(wrow + d) * DD + kofs + k];
        }
        __syncthreads();

        float acc[8][4];
#pragma unroll
        for (int i = 0; i < 8; i++)
#pragma unroll
            for (int j = 0; j < 4; j++) acc[i][j] = 0.f;

#pragma unroll 2
        for (int k = 0; k < EMB; k += 4) {
            float4 wv0 = *(const float4*)&W_s[(k + 0) * WS_STRIDE + d0];
            float4 wv1 = *(const float4*)&W_s[(k + 1) * WS_STRIDE + d0];
            float4 wv2 = *(const float4*)&W_s[(k + 2) * WS_STRIDE + d0];
            float4 wv3 = *(const float4*)&W_s[(k + 3) * WS_STRIDE + d0];
#pragma unroll
            for (int i = 0; i < 8; i++) {
                float4 a = *(const float4*)&A_s[(r0 + i) * AS_STRIDE + k];
                acc[i][0] += a.x * wv0.x + a.y * wv1.x + a.z * wv2.x + a.w * wv3.x;
                acc[i][1] += a.x * wv0.y + a.y * wv1.y + a.z * wv2.y + a.w * wv3.y;
                acc[i][2] += a.x * wv0.z + a.y * wv1.z + a.z * wv2.z + a.w * wv3.z;
                acc[i][3] += a.x * wv0.w + a.y * wv1.w + a.z * wv2.w + a.w * wv3.w;
            }
        }
#pragma unroll
        for (int i = 0; i < 8; i++) {
            int r = v0 + r0 + i;
            if (r < nv) {
                float4 o = make_float4(acc[i][0], acc[i][1], acc[i][2], acc[i][3]);
                *(float4*)&outp[r * ostride + dbase + d0] = o;
            }
        }
    }
}

// ----------------------------------------------------------------
// K1b: per (b,s): f_proj = feat @ Wt4^T + bt; per context l:
//   cw = ba + sum_d Wa[d]*tanh(Tn_s[si][d]+Tn_e[ei][d]+Tp[pi][d]+fproj[d])
// Each warp handles TWO contexts (l, l+50).
// ----------------------------------------------------------------
__global__ void __launch_bounds__(256)
k1b_cw(const float* __restrict__ x,
       const float* __restrict__ Wt,
       const float* __restrict__ bt,
       const float* __restrict__ Wa,
       const float* __restrict__ ba)
{
    __shared__ int si[LL], pi[LL], ei[LL];
    __shared__ float4 fproj4[DD/4], was4[DD/4];
    __shared__ float feat_s[FEAT];
    float* fproj = (float*)fproj4;
    float* was   = (float*)was4;

    const int bs = blockIdx.x;
    const int b = bs / SS, s = bs % SS;
    const int t = threadIdx.x;

    if (t < LL) {
        int xb = bs * DD + FEAT + 3 * t;
        si[t] = (int)x[xb];
        pi[t] = (int)x[xb + 1];
        ei[t] = (int)x[xb + 2];
    }
    if (t < FEAT) feat_s[t] = x[bs * DD + t];
    __syncthreads();

    for (int d = t; d < DD; d += 256) {
        float acc = bt[d];
        const float* wrow = &Wt[d * DD + 300];
#pragma unroll
        for (int k = 0; k < FEAT; k++) acc += feat_s[k] * wrow[k];
        fproj[d] = acc;
        was[d] = Wa[d];
    }
    __syncthreads();

    const int warp = t >> 5, lane = t & 31;
    const float bav = ba[0];
    for (int l0 = warp; l0 < 50; l0 += 8) {
        const int l1 = l0 + 50;
        const float4* pn0 = (const float4*)&g_Tn[si[l0] * 640];
        const float4* pe0 = (const float4*)&g_Tn[ei[l0] * 640 + 320];
        const float4* pp0 = (const float4*)&g_Tp[pi[l0] * 320];
        const float4* pn1 = (const float4*)&g_Tn[si[l1] * 640];
        const float4* pe1 = (const float4*)&g_Tn[ei[l1] * 640 + 320];
        const float4* pp1 = (const float4*)&g_Tp[pi[l1] * 320];
        float sum0 = 0.f, sum1 = 0.f;
        for (int j = lane; j < DD/4; j += 32) {
            float4 f = fproj4[j], w = was4[j];
            float4 a0 = pn0[j], b0 = pe0[j], c0 = pp0[j];
            float4 a1 = pn1[j], b1 = pe1[j], c1 = pp1[j];
            sum0 += w.x * tanh_fast(a0.x + b0.x + c0.x + f.x)
                  + w.y * tanh_fast(a0.y + b0.y + c0.y + f.y)
                  + w.z * tanh_fast(a0.z + b0.z + c0.z + f.z)
                  + w.w * tanh_fast(a0.w + b0.w + c0.w + f.w);
            sum1 += w.x * tanh_fast(a1.x + b1.x + c1.x + f.x)
                  + w.y * tanh_fast(a1.y + b1.y + c1.y + f.y)
                  + w.z * tanh_fast(a1.z + b1.z + c1.z + f.z)
                  + w.w * tanh_fast(a1.w + b1.w + c1.w + f.w);
        }
#pragma unroll
        for (int off = 16; off; off >>= 1) {
            sum0 += __shfl_xor_sync(~0u, sum0, off);
            sum1 += __shfl_xor_sync(~0u, sum1, off);
        }
        if (lane == 0) {
            g_cw[(b * LL + l0) * SS + s] = sum0 + bav;
            g_cw[(b * LL + l1) * SS + s] = sum1 + bav;
        }
    }
}

// ----------------------------------------------------------------
// K2: softmax over s (axis=1) for each (b,l); write aw in [b][s][l]
// ----------------------------------------------------------------
__global__ void k2_softmax() {
    const int bl = blockIdx.x;
    const int t  = threadIdx.x;    // 128
    const float* row = g_cw + bl * SS;
    float v0 = (t < SS) ? row[t] : -3.0e38f;

    __shared__ float sw[4];
    float v = v0;
#pragma unroll
    for (int off = 16; off; off >>= 1) v = fmaxf(v, __shfl_xor_sync(~0u, v, off));
    if ((t & 31) == 0) sw[t >> 5] = v;
    __syncthreads();
    float mx = fmaxf(fmaxf(sw[0], sw[1]), fmaxf(sw[2], sw[3]));
    __syncthreads();

    float e = (t < SS) ? expf(v0 - mx) : 0.f;
    float sv = e;
#pragma unroll
    for (int off = 16; off; off >>= 1) sv += __shfl_xor_sync(~0u, sv, off);
    if ((t & 31) == 0) sw[t >> 5] = sv;
    __syncthreads();
    float tot = sw[0] + sw[1] + sw[2] + sw[3];

    if (t < SS) {
        int b = bl / LL, l = bl % LL;
        g_aw[(b * SS + t) * LL + l] = e / tot;
    }
}

// ----------------------------------------------------------------
// K3: code_vec via re-gather; rnn_in = [feat(20), code_vec(320)]
// ----------------------------------------------------------------
__global__ void k3_codevec(const float* __restrict__ x,
                           const float* __restrict__ etab_n,
                           const float* __restrict__ etab_p)
{
    __shared__ float aw_s[LL];
    __shared__ int si[LL], pi[LL], ei[LL];
    __shared__ float awsum_s;
    const int bs = blockIdx.x;
    const int t  = threadIdx.x;   // 128

    if (t < LL) {
        aw_s[t] = g_aw[bs * LL + t];
        int xb = bs * DD + FEAT + 3 * t;
        si[t] = (int)x[xb];
        pi[t] = (int)x[xb + 1];
        ei[t] = (int)x[xb + 2];
    }
    __syncthreads();
    if (t == 0) {
        float a = 0.f;
        for (int l = 0; l < LL; l++) a += aw_s[l];
        awsum_s = a;
    }
    __syncthreads();

    float* outrow = g_rnn + bs * RNNIN;
    for (int j = t; j < RNNIN; j += 128) {
        float v;
        if (j < FEAT) {
            v = x[bs * DD + j];
        } else {
            int k = j - FEAT;
            float acc = 0.f;
            if (k < EMB) {
                for (int l = 0; l < LL; l++) acc += etab_n[si[l] * EMB + k] * aw_s[l];
            } else if (k < 2 * EMB) {
                int km = k - EMB;
                for (int l = 0; l < LL; l++) acc += etab_n[ei[l] * EMB + km] * aw_s[l];
            } else if (k < 3 * EMB) {
                int km = k - 2 * EMB;
                for (int l = 0; l < LL; l++) acc += etab_p[pi[l] * EMB + km] * aw_s[l];
            } else {
                acc = x[bs * DD + (k - 3 * EMB)] * awsum_s;
            }
            v = acc;
        }
        outrow[j] = v;
    }
}

// ----------------------------------------------------------------
// K4: g_gx = rnn_in @ W_ih^T + b_ih + b_hh  (coalesced WihT scalar loads)
// ----------------------------------------------------------------
__global__ void __launch_bounds__(512)
k4_gates(const float* __restrict__ bih, const float* __restrict__ bhh)
{
    __shared__ float A_s[16 * RNNIN];
    const int n  = threadIdx.x;
    const int r0 = blockIdx.x * 16;

    for (int e = n; e < 16 * RNNIN; e += 512)
        A_s[e] = g_rnn[r0 * RNNIN + e];
    __syncthreads();

    float acc[16];
#pragma unroll
    for (int i = 0; i < 16; i++) acc[i] = 0.f;

#pragma unroll 2
    for (int k = 0; k < RNNIN; k += 4) {
        float w0 = g_WihT[(k + 0) * G4 + n];
        float w1 = g_WihT[(k + 1) * G4 + n];
        float w2 = g_WihT[(k + 2) * G4 + n];
        float w3 = g_WihT[(k + 3) * G4 + n];
#pragma unroll
        for (int i = 0; i < 16; i++) {
            float4 a = *(const float4*)&A_s[i * RNNIN + k];
            acc[i] += a.x * w0 + a.y * w1 + a.z * w2 + a.w * w3;
        }
    }
    float bias = bih[n] + bhh[n];
#pragma unroll
    for (int i = 0; i < 16; i++)
        g_gx[(r0 + i) * G4 + n] = acc[i] + bias;
}

// ----------------------------------------------------------------
// K5: LSTM recurrence, W_hh mostly smem-resident.
// smem: W_s (104 k-slices, 213 KB) + red (8 KB) + h (0.5 KB).
// Remaining 24 k-slices stream via LDG (latency hidden by LDS work).
// ----------------------------------------------------------------
#define K5_SMEM ((KSM*HID + 4*HID) * 16 + HID * 4)

__global__ void __launch_bounds__(512)
k5_lstm()
{
    extern __shared__ float4 sm4[];
    float4* W_s = sm4;                    // KSM*128 float4
    float4* red = sm4 + KSM * HID;        // 4*128 float4
    float*  h_s = (float*)(red + 4 * HID);

    const int b = blockIdx.x;
    const int n = threadIdx.x & 127;
    const int q = threadIdx.x >> 7;

    // prologue: stage first KSM k-slices of W into smem (coalesced)
    for (int e = threadIdx.x; e < KSM * HID; e += 512)
        W_s[e] = g_Whh4[e];
    if (threadIdx.x < HID) h_s[threadIdx.x] = 0.f;
    float c = 0.f;
    __syncthreads();

    for (int s = 0; s < SS; s++) {
        float4 acc = make_float4(0.f, 0.f, 0.f, 0.f);
        const float* hq = &h_s[q * 32];
        if (q < 3) {
            const float4* wb = &W_s[q * 32 * HID + n];
#pragma unroll 8
            for (int kk = 0; kk < 32; kk++) {
                float4 w = wb[kk * HID];
                float hk = hq[kk];
                acc.x += w.x * hk; acc.y += w.y * hk;
                acc.z += w.z * hk; acc.w += w.w * hk;
            }
        } else {
            const float4* wbs = &W_s[96 * HID + n];          // k = 96..103 (smem)
            const float4* wbg = &g_Whh4[KSM * HID + n];      // k = 104..127 (global)
#pragma unroll
            for (int kk = 0; kk < 8; kk++) {
                float4 w = wbs[kk * HID];
                float hk = hq[kk];
                acc.x += w.x * hk; acc.y += w.y * hk;
                acc.z += w.z * hk; acc.w += w.w * hk;
            }
#pragma unroll 8
            for (int kk = 0; kk < 24; kk++) {
                float4 w = wbg[kk * HID];
                float hk = hq[8 + kk];
                acc.x += w.x * hk; acc.y += w.y * hk;
                acc.z += w.z * hk; acc.w += w.w * hk;
            }
        }
        red[q * HID + n] = acc;
        __syncthreads();
        if (threadIdx.x < HID) {
            float4 a0 = red[0 * HID + threadIdx.x];
            float4 a1 = red[1 * HID + threadIdx.x];
            float4 a2 = red[2 * HID + threadIdx.x];
            float4 a3 = red[3 * HID + threadIdx.x];
            const float* gx = &g_gx[(b * SS + s) * G4];
            float gi = a0.x + a1.x + a2.x + a3.x + gx[threadIdx.x];
            float gf = a0.y + a1.y + a2.y + a3.y + gx[HID + threadIdx.x];
            float gg = a0.z + a1.z + a2.z + a3.z + gx[2 * HID + threadIdx.x];
            float go = a0.w + a1.w + a2.w + a3.w + gx[3 * HID + threadIdx.x];
            c = sigf(gf) * c + sigf(gi) * tanhf(gg);
            float h = sigf(go) * tanhf(c);
            h_s[threadIdx.x] = h;
            g_hs[(b * SS + s) * HID + threadIdx.x] = h;
        }
        __syncthreads();
    }
}

// ----------------------------------------------------------------
// K6: out = sigmoid(hs @ W_fc^T + b_fc)
// ----------------------------------------------------------------
__global__ void k6_fc(const float* __restrict__ Wfc,
                      const float* __restrict__ bfc,
                      float* __restrict__ out)
{
    int t = blockIdx.x * blockDim.x + threadIdx.x;
    if (t >= BB * SS * NOUT) return;
    int bs = t / NOUT;
    int o  = t % NOUT;
    const float* hrow = g_hs + bs * HID;
    const float* wrow = Wfc + o * HID;
    float acc = bfc[o];
#pragma unroll 8
    for (int u = 0; u < HID; u++) acc += hrow[u] * wrow[u];
    out[t] = sigf(acc);
}

// ----------------------------------------------------------------
extern "C" void kernel_launch(void* const* d_in, const int* in_sizes, int n_in,
                              void* d_out, int out_size)
{
    const float* x      = (const float*)d_in[0];
    const float* etab_n = (const float*)d_in[1];
    const float* etab_p = (const float*)d_in[2];
    const float* Wt     = (const float*)d_in[3];
    const float* bt     = (const float*)d_in[4];
    const float* Wa     = (const float*)d_in[5];
    const float* ba     = (const float*)d_in[6];
    const float* Wih    = (const float*)d_in[7];
    const float* Whh    = (const float*)d_in[8];
    const float* bih    = (const float*)d_in[9];
    const float* bhh    = (const float*)d_in[10];
    const float* Wfc    = (const float*)d_in[11];
    const float* bfc    = (const float*)d_in[12];
    float* out = (float*)d_out;

    const int kp_smem = (128 * AS_STRIDE + 100 * WS_STRIDE) * 4;
    cudaFuncSetAttribute(kp_project, cudaFuncAttributeMaxDynamicSharedMemorySize, kp_smem);
    cudaFuncSetAttribute(k5_lstm, cudaFuncAttributeMaxDynamicSharedMemorySize, K5_SMEM);

    {
        int total = RNNIN * G4;
        k0_transpose<<<(total + 255) / 256, 256>>>(Wih, Whh);     // 1
    }
    kp_project<<<PROJ_NODE_BLOCKS + PROJ_PATH_BLOCKS, 256, kp_smem>>>(etab_n, etab_p, Wt); // 2
    k1b_cw<<<BB * SS, 256>>>(x, Wt, bt, Wa, ba);                  // 3
    k2_softmax<<<BB * LL, 128>>>();                               // 4
    k3_codevec<<<BB * SS, 128>>>(x, etab_n, etab_p);              // 5
    k4_gates<<<BB * SS / 16, 512>>>(bih, bhh);                    // 6
    k5_lstm<<<BB, 512, K5_SMEM>>>();                              // 7
    {
        int total = BB * SS * NOUT;
        k6_fc<<<(total + 255) / 256, 256>>>(Wfc, bfc, out);       // 8
    }
}

// round 16
// speedup vs baseline: 1.2657x; 1.0468x over previous
#include <cuda_runtime.h>
#include <cuda_bf16.h>
#include <math.h>

// Problem dims
#define BB 16
#define SS 100
#define LL 100          // MAX_CODE_LEN
#define FEAT 20         // INPUT_DIM
#define EMB 100
#define DD 320          // D = 20 + 3*100
#define RNNIN 340       // 2*20 + 3*100
#define HID 128
#define G4 512
#define NOUT 10

#define NVOC_N 10002
#define NVOC_P 50002
#define PROJ_NODE_BLOCKS 79   // ceil(10002/128)
#define PROJ_PATH_BLOCKS 391  // ceil(50002/128)
#define WS_STRIDE 68          // multiple of 4: float4 stays 16B-aligned
#define AS_STRIDE 104         // multiple of 4

#define KSM 104               // k-slices of W_hh resident in smem (of 128)

// -------- scratch (device globals; no allocation allowed) --------
static __device__ __nv_bfloat16 g_Tn[NVOC_N * 640];  // bf16: [v][0:320]=start proj, [v][320:640]=end proj
static __device__ __nv_bfloat16 g_Tp[NVOC_P * 320];  // bf16 path proj
static __device__ float g_cw[BB*LL*SS];        // [b][l][s]
static __device__ float g_aw[BB*SS*LL];        // [b][s][l]
static __device__ float g_rnn[BB*SS*RNNIN];    // [b][s][340]
static __device__ float g_gx[BB*SS*G4];        // x-part gates
static __device__ float g_hs[BB*SS*HID];       // lstm outputs
static __device__ float g_WihT[RNNIN*G4];      // [k][n] coalesced
static __device__ float4 g_Whh4[HID*HID];      // [k][n] -> gates (i,f,g,o) packed

__device__ __forceinline__ float sigf(float x) { return 1.0f / (1.0f + expf(-x)); }
__device__ __forceinline__ float tanh_fast(float x) {
    float y;
    asm("tanh.approx.f32 %0, %1;" : "=f"(y) : "f"(x));
    return y;
}
__device__ __forceinline__ float2 bf2f(unsigned u) {
    __nv_bfloat162 h = *reinterpret_cast<__nv_bfloat162*>(&u);
    return __bfloat1622float2(h);
}
__device__ __forceinline__ unsigned f2bf(float a, float b) {
    __nv_bfloat162 h = __float22bfloat162_rn(make_float2(a, b));
    return *reinterpret_cast<unsigned*>(&h);
}

// ----------------------------------------------------------------
// K0: transpose W_ih; pack W_hh by gate quadruple
// ----------------------------------------------------------------
__global__ void k0_transpose(const float* __restrict__ Wih, const float* __restrict__ Whh) {
    int t = blockIdx.x * blockDim.x + threadIdx.x;
    if (t < RNNIN * G4) {          // Wih is [512][340]
        int n = t / RNNIN, k = t % RNNIN;
        g_WihT[k * G4 + n] = Wih[t];
    }
    if (t < HID * HID) {           // Whh is [512][128]: rows g*128+n, cols k
        int k = t / HID, n = t % HID;
        g_Whh4[k * HID + n] = make_float4(
            Whh[(0 * HID + n) * HID + k],
            Whh[(1 * HID + n) * HID + k],
            Whh[(2 * HID + n) * HID + k],
            Whh[(3 * HID + n) * HID + k]);
    }
}

// ----------------------------------------------------------------
// KP: project embedding tables through W_trans column blocks.
// Output stored as bf16 (tables become L2-resident; k1b traffic halves).
// ----------------------------------------------------------------
__global__ void __launch_bounds__(256, 1)
kp_project(const float* __restrict__ etab_n,
           const float* __restrict__ etab_p,
           const float* __restrict__ Wt)
{
    extern __shared__ float sm[];
    float* A_s = sm;                        // 128 * 104
    float* W_s = sm + 128 * AS_STRIDE;      // 100 * 68

    const int t = threadIdx.x;
    const bool isnode = blockIdx.x < PROJ_NODE_BLOCKS;
    const int vb = isnode ? blockIdx.x : blockIdx.x - PROJ_NODE_BLOCKS;
    const int v0 = vb * 128;
    const int nv = isnode ? NVOC_N : NVOC_P;
    const float* tab = isnode ? etab_n : etab_p;
    __nv_bfloat16* outp = isnode ? g_Tn : g_Tp;
    const int ostride = isnode ? 640 : 320;
    const int ndb = isnode ? 10 : 5;

    for (int e = t; e < 128 * EMB; e += 256) {
        int r = e / EMB, k = e % EMB;
        float v = 0.f;
        if (v0 + r < nv) v = tab[(v0 + r) * EMB + k];
        A_s[r * AS_STRIDE + k] = v;
    }

    const int tx = t & 15;
    const int ty = t >> 4;
    const int d0 = tx * 4;
    const int r0 = ty * 8;

    for (int db = 0; db < ndb; db++) {
        const int dbase = db * 64;
        int wrow, kofs;
        if (isnode) {
            if (db < 5) { wrow = dbase;       kofs = 0;   }
            else        { wrow = dbase - 320; kofs = 100; }
        } else          { wrow = dbase;       kofs = 200; }

        __syncthreads();
        for (int e = t; e < 64 * EMB; e += 256) {
            int d = e / EMB, k = e % EMB;
            W_s[k * WS_STRIDE + d] = Wt[(wrow + d) * DD + kofs + k];
        }
        __syncthreads();

        float acc[8][4];
#pragma unroll
        for (int i = 0; i < 8; i++)
#pragma unroll
            for (int j = 0; j < 4; j++) acc[i][j] = 0.f;

#pragma unroll 2
        for (int k = 0; k < EMB; k += 4) {
            float4 wv0 = *(const float4*)&W_s[(k + 0) * WS_STRIDE + d0];
            float4 wv1 = *(const float4*)&W_s[(k + 1) * WS_STRIDE + d0];
            float4 wv2 = *(const float4*)&W_s[(k + 2) * WS_STRIDE + d0];
            float4 wv3 = *(const float4*)&W_s[(k + 3) * WS_STRIDE + d0];
#pragma unroll
            for (int i = 0; i < 8; i++) {
                float4 a = *(const float4*)&A_s[(r0 + i) * AS_STRIDE + k];
                acc[i][0] += a.x * wv0.x + a.y * wv1.x + a.z * wv2.x + a.w * wv3.x;
                acc[i][1] += a.x * wv0.y + a.y * wv1.y + a.z * wv2.y + a.w * wv3.y;
                acc[i][2] += a.x * wv0.z + a.y * wv1.z + a.z * wv2.z + a.w * wv3.z;
                acc[i][3] += a.x * wv0.w + a.y * wv1.w + a.z * wv2.w + a.w * wv3.w;
            }
        }
#pragma unroll
        for (int i = 0; i < 8; i++) {
            int r = v0 + r0 + i;
            if (r < nv) {
                uint2 o;
                o.x = f2bf(acc[i][0], acc[i][1]);
                o.y = f2bf(acc[i][2], acc[i][3]);
                *(uint2*)&outp[r * ostride + dbase + d0] = o;   // 8B-aligned (d0 mult of 4)
            }
        }
    }
}

// ----------------------------------------------------------------
// K1b: per (b,s): f_proj = feat @ Wt4^T + bt; per context l:
//   cw = ba + sum_d Wa[d]*tanh(Tn_s[si][d]+Tn_e[ei][d]+Tp[pi][d]+fproj[d])
// bf16 table gathers (uint4 = 8 elems); two contexts per warp.
// ----------------------------------------------------------------
__global__ void __launch_bounds__(256)
k1b_cw(const float* __restrict__ x,
       const float* __restrict__ Wt,
       const float* __restrict__ bt,
       const float* __restrict__ Wa,
       const float* __restrict__ ba)
{
    __shared__ int si[LL], pi[LL], ei[LL];
    __shared__ float4 fproj4[DD/4], was4[DD/4];
    __shared__ float feat_s[FEAT];
    float* fproj = (float*)fproj4;
    float* was   = (float*)was4;

    const int bs = blockIdx.x;
    const int b = bs / SS, s = bs % SS;
    const int t = threadIdx.x;

    if (t < LL) {
        int xb = bs * DD + FEAT + 3 * t;
        si[t] = (int)x[xb];
        pi[t] = (int)x[xb + 1];
        ei[t] = (int)x[xb + 2];
    }
    if (t < FEAT) feat_s[t] = x[bs * DD + t];
    __syncthreads();

    for (int d = t; d < DD; d += 256) {
        float acc = bt[d];
        const float* wrow = &Wt[d * DD + 300];
#pragma unroll
        for (int k = 0; k < FEAT; k++) acc += feat_s[k] * wrow[k];
        fproj[d] = acc;
        was[d] = Wa[d];
    }
    __syncthreads();

    const int warp = t >> 5, lane = t & 31;
    const float bav = ba[0];
    for (int l0 = warp; l0 < 50; l0 += 8) {
        const int l1 = l0 + 50;
        const uint4* pn0 = (const uint4*)&g_Tn[si[l0] * 640];
        const uint4* pe0 = (const uint4*)&g_Tn[ei[l0] * 640 + 320];
        const uint4* pp0 = (const uint4*)&g_Tp[pi[l0] * 320];
        const uint4* pn1 = (const uint4*)&g_Tn[si[l1] * 640];
        const uint4* pe1 = (const uint4*)&g_Tn[ei[l1] * 640 + 320];
        const uint4* pp1 = (const uint4*)&g_Tp[pi[l1] * 320];
        float sum0 = 0.f, sum1 = 0.f;
        // 40 chunks of 8 elems cover DD=320
        for (int j = lane; j < DD/8; j += 32) {
            float4 f0 = fproj4[2*j], f1 = fproj4[2*j+1];
            float4 w0 = was4[2*j],   w1 = was4[2*j+1];
            {
                uint4 an = pn0[j], ae = pe0[j], ap = pp0[j];
                float2 nA = bf2f(an.x), eA = bf2f(ae.x), pA = bf2f(ap.x);
                float2 nB = bf2f(an.y), eB = bf2f(ae.y), pB = bf2f(ap.y);
                float2 nC = bf2f(an.z), eC = bf2f(ae.z), pC = bf2f(ap.z);
                float2 nD = bf2f(an.w), eD = bf2f(ae.w), pD = bf2f(ap.w);
                sum0 += w0.x * tanh_fast(nA.x + eA.x + pA.x + f0.x)
                      + w0.y * tanh_fast(nA.y + eA.y + pA.y + f0.y)
                      + w0.z * tanh_fast(nB.x + eB.x + pB.x + f0.z)
                      + w0.w * tanh_fast(nB.y + eB.y + pB.y + f0.w)
                      + w1.x * tanh_fast(nC.x + eC.x + pC.x + f1.x)
                      + w1.y * tanh_fast(nC.y + eC.y + pC.y + f1.y)
                      + w1.z * tanh_fast(nD.x + eD.x + pD.x + f1.z)
                      + w1.w * tanh_fast(nD.y + eD.y + pD.y + f1.w);
            }
            {
                uint4 an = pn1[j], ae = pe1[j], ap = pp1[j];
                float2 nA = bf2f(an.x), eA = bf2f(ae.x), pA = bf2f(ap.x);
                float2 nB = bf2f(an.y), eB = bf2f(ae.y), pB = bf2f(ap.y);
                float2 nC = bf2f(an.z), eC = bf2f(ae.z), pC = bf2f(ap.z);
                float2 nD = bf2f(an.w), eD = bf2f(ae.w), pD = bf2f(ap.w);
                sum1 += w0.x * tanh_fast(nA.x + eA.x + pA.x + f0.x)
                      + w0.y * tanh_fast(nA.y + eA.y + pA.y + f0.y)
                      + w0.z * tanh_fast(nB.x + eB.x + pB.x + f0.z)
                      + w0.w * tanh_fast(nB.y + eB.y + pB.y + f0.w)
                      + w1.x * tanh_fast(nC.x + eC.x + pC.x + f1.x)
                      + w1.y * tanh_fast(nC.y + eC.y + pC.y + f1.y)
                      + w1.z * tanh_fast(nD.x + eD.x + pD.x + f1.z)
                      + w1.w * tanh_fast(nD.y + eD.y + pD.y + f1.w);
            }
        }
#pragma unroll
        for (int off = 16; off; off >>= 1) {
            sum0 += __shfl_xor_sync(~0u, sum0, off);
            sum1 += __shfl_xor_sync(~0u, sum1, off);
        }
        if (lane == 0) {
            g_cw[(b * LL + l0) * SS + s] = sum0 + bav;
            g_cw[(b * LL + l1) * SS + s] = sum1 + bav;
        }
    }
}

// ----------------------------------------------------------------
// K2: softmax over s (axis=1) for each (b,l); write aw in [b][s][l]
// ----------------------------------------------------------------
__global__ void k2_softmax() {
    const int bl = blockIdx.x;
    const int t  = threadIdx.x;    // 128
    const float* row = g_cw + bl * SS;
    float v0 = (t < SS) ? row[t] : -3.0e38f;

    __shared__ float sw[4];
    float v = v0;
#pragma unroll
    for (int off = 16; off; off >>= 1) v = fmaxf(v, __shfl_xor_sync(~0u, v, off));
    if ((t & 31) == 0) sw[t >> 5] = v;
    __syncthreads();
    float mx = fmaxf(fmaxf(sw[0], sw[1]), fmaxf(sw[2], sw[3]));
    __syncthreads();

    float e = (t < SS) ? expf(v0 - mx) : 0.f;
    float sv = e;
#pragma unroll
    for (int off = 16; off; off >>= 1) sv += __shfl_xor_sync(~0u, sv, off);
    if ((t & 31) == 0) sw[t >> 5] = sv;
    __syncthreads();
    float tot = sw[0] + sw[1] + sw[2] + sw[3];

    if (t < SS) {
        int b = bl / LL, l = bl % LL;
        g_aw[(b * SS + t) * LL + l] = e / tot;
    }
}

// ----------------------------------------------------------------
// K3: code_vec via re-gather (fp32 embedding tables — exact);
// rnn_in = [feat(20), code_vec(320)]
// ----------------------------------------------------------------
__global__ void k3_codevec(const float* __restrict__ x,
                           const float* __restrict__ etab_n,
                           const float* __restrict__ etab_p)
{
    __shared__ float aw_s[LL];
    __shared__ int si[LL], pi[LL], ei[LL];
    __shared__ float awsum_s;
    const int bs = blockIdx.x;
    const int t  = threadIdx.x;   // 128

    if (t < LL) {
        aw_s[t] = g_aw[bs * LL + t];
        int xb = bs * DD + FEAT + 3 * t;
        si[t] = (int)x[xb];
        pi[t] = (int)x[xb + 1];
        ei[t] = (int)x[xb + 2];
    }
    __syncthreads();
    if (t == 0) {
        float a = 0.f;
        for (int l = 0; l < LL; l++) a += aw_s[l];
        awsum_s = a;
    }
    __syncthreads();

    float* outrow = g_rnn + bs * RNNIN;
    for (int j = t; j < RNNIN; j += 128) {
        float v;
        if (j < FEAT) {
            v = x[bs * DD + j];
        } else {
            int k = j - FEAT;
            float acc = 0.f;
            if (k < EMB) {
                for (int l = 0; l < LL; l++) acc += etab_n[si[l] * EMB + k] * aw_s[l];
            } else if (k < 2 * EMB) {
                int km = k - EMB;
                for (int l = 0; l < LL; l++) acc += etab_n[ei[l] * EMB + km] * aw_s[l];
            } else if (k < 3 * EMB) {
                int km = k - 2 * EMB;
                for (int l = 0; l < LL; l++) acc += etab_p[pi[l] * EMB + km] * aw_s[l];
            } else {
                acc = x[bs * DD + (k - 3 * EMB)] * awsum_s;
            }
            v = acc;
        }
        outrow[j] = v;
    }
}

// ----------------------------------------------------------------
// K4: g_gx = rnn_in @ W_ih^T + b_ih + b_hh  (coalesced WihT scalar loads)
// ----------------------------------------------------------------
__global__ void __launch_bounds__(512)
k4_gates(const float* __restrict__ bih, const float* __restrict__ bhh)
{
    __shared__ float A_s[16 * RNNIN];
    const int n  = threadIdx.x;
    const int r0 = blockIdx.x * 16;

    for (int e = n; e < 16 * RNNIN; e += 512)
        A_s[e] = g_rnn[r0 * RNNIN + e];
    __syncthreads();

    float acc[16];
#pragma unroll
    for (int i = 0; i < 16; i++) acc[i] = 0.f;

#pragma unroll 2
    for (int k = 0; k < RNNIN; k += 4) {
        float w0 = g_WihT[(k + 0) * G4 + n];
        float w1 = g_WihT[(k + 1) * G4 + n];
        float w2 = g_WihT[(k + 2) * G4 + n];
        float w3 = g_WihT[(k + 3) * G4 + n];
#pragma unroll
        for (int i = 0; i < 16; i++) {
            float4 a = *(const float4*)&A_s[i * RNNIN + k];
            acc[i] += a.x * w0 + a.y * w1 + a.z * w2 + a.w * w3;
        }
    }
    float bias = bih[n] + bhh[n];
#pragma unroll
    for (int i = 0; i < 16; i++)
        g_gx[(r0 + i) * G4 + n] = acc[i] + bias;
}

// ----------------------------------------------------------------
// K5: LSTM recurrence, W_hh mostly smem-resident.
// ----------------------------------------------------------------
#define K5_SMEM ((KSM*HID + 4*HID) * 16 + HID * 4)

__global__ void __launch_bounds__(512)
k5_lstm()
{
    extern __shared__ float4 sm4[];
    float4* W_s = sm4;                    // KSM*128 float4
    float4* red = sm4 + KSM * HID;        // 4*128 float4
    float*  h_s = (float*)(red + 4 * HID);

    const int b = blockIdx.x;
    const int n = threadIdx.x & 127;
    const int q = threadIdx.x >> 7;

    for (int e = threadIdx.x; e < KSM * HID; e += 512)
        W_s[e] = g_Whh4[e];
    if (threadIdx.x < HID) h_s[threadIdx.x] = 0.f;
    float c = 0.f;
    __syncthreads();

    for (int s = 0; s < SS; s++) {
        float4 acc = make_float4(0.f, 0.f, 0.f, 0.f);
        const float* hq = &h_s[q * 32];
        if (q < 3) {
            const float4* wb = &W_s[q * 32 * HID + n];
#pragma unroll 8
            for (int kk = 0; kk < 32; kk++) {
                float4 w = wb[kk * HID];
                float hk = hq[kk];
                acc.x += w.x * hk; acc.y += w.y * hk;
                acc.z += w.z * hk; acc.w += w.w * hk;
            }
        } else {
            const float4* wbs = &W_s[96 * HID + n];          // k = 96..103 (smem)
            const float4* wbg = &g_Whh4[KSM * HID + n];      // k = 104..127 (global)
#pragma unroll
            for (int kk = 0; kk < 8; kk++) {
                float4 w = wbs[kk * HID];
                float hk = hq[kk];
                acc.x += w.x * hk; acc.y += w.y * hk;
                acc.z += w.z * hk; acc.w += w.w * hk;
            }
#pragma unroll 8
            for (int kk = 0; kk < 24; kk++) {
                float4 w = wbg[kk * HID];
                float hk = hq[8 + kk];
                acc.x += w.x * hk; acc.y += w.y * hk;
                acc.z += w.z * hk; acc.w += w.w * hk;
            }
        }
        red[q * HID + n] = acc;
        __syncthreads();
        if (threadIdx.x < HID) {
            float4 a0 = red[0 * HID + threadIdx.x];
            float4 a1 = red[1 * HID + threadIdx.x];
            float4 a2 = red[2 * HID + threadIdx.x];
            float4 a3 = red[3 * HID + threadIdx.x];
            const float* gx = &g_gx[(b * SS + s) * G4];
            float gi = a0.x + a1.x + a2.x + a3.x + gx[threadIdx.x];
            float gf = a0.y + a1.y + a2.y + a3.y + gx[HID + threadIdx.x];
            float gg = a0.z + a1.z + a2.z + a3.z + gx[2 * HID + threadIdx.x];
            float go = a0.w + a1.w + a2.w + a3.w + gx[3 * HID + threadIdx.x];
            c = sigf(gf) * c + sigf(gi) * tanhf(gg);
            float h = sigf(go) * tanhf(c);
            h_s[threadIdx.x] = h;
            g_hs[(b * SS + s) * HID + threadIdx.x] = h;
        }
        __syncthreads();
    }
}

// ----------------------------------------------------------------
// K6: out = sigmoid(hs @ W_fc^T + b_fc)
// ----------------------------------------------------------------
__global__ void k6_fc(const float* __restrict__ Wfc,
                      const float* __restrict__ bfc,
                      float* __restrict__ out)
{
    int t = blockIdx.x * blockDim.x + threadIdx.x;
    if (t >= BB * SS * NOUT) return;
    int bs = t / NOUT;
    int o  = t % NOUT;
    const float* hrow = g_hs + bs * HID;
    const float* wrow = Wfc + o * HID;
    float acc = bfc[o];
#pragma unroll 8
    for (int u = 0; u < HID; u++) acc += hrow[u] * wrow[u];
    out[t] = sigf(acc);
}

// ----------------------------------------------------------------
extern "C" void kernel_launch(void* const* d_in, const int* in_sizes, int n_in,
                              void* d_out, int out_size)
{
    const float* x      = (const float*)d_in[0];
    const float* etab_n = (const float*)d_in[1];
    const float* etab_p = (const float*)d_in[2];
    const float* Wt     = (const float*)d_in[3];
    const float* bt     = (const float*)d_in[4];
    const float* Wa     = (const float*)d_in[5];
    const float* ba     = (const float*)d_in[6];
    const float* Wih    = (const float*)d_in[7];
    const float* Whh    = (const float*)d_in[8];
    const float* bih    = (const float*)d_in[9];
    const float* bhh    = (const float*)d_in[10];
    const float* Wfc    = (const float*)d_in[11];
    const float* bfc    = (const float*)d_in[12];
    float* out = (float*)d_out;

    const int kp_smem = (128 * AS_STRIDE + 100 * WS_STRIDE) * 4;
    cudaFuncSetAttribute(kp_project, cudaFuncAttributeMaxDynamicSharedMemorySize, kp_smem);
    cudaFuncSetAttribute(k5_lstm, cudaFuncAttributeMaxDynamicSharedMemorySize, K5_SMEM);

    {
        int total = RNNIN * G4;
        k0_transpose<<<(total + 255) / 256, 256>>>(Wih, Whh);     // 1
    }
    kp_project<<<PROJ_NODE_BLOCKS + PROJ_PATH_BLOCKS, 256, kp_smem>>>(etab_n, etab_p, Wt); // 2
    k1b_cw<<<BB * SS, 256>>>(x, Wt, bt, Wa, ba);                  // 3
    k2_softmax<<<BB * LL, 128>>>();                               // 4
    k3_codevec<<<BB * SS, 128>>>(x, etab_n, etab_p);              // 5
    k4_gates<<<BB * SS / 16, 512>>>(bih, bhh);                    // 6
    k5_lstm<<<BB, 512, K5_SMEM>>>();                              // 7
    {
        int total = BB * SS * NOUT;
        k6_fc<<<(total + 255) / 256, 256>>>(Wfc, bfc, out);       // 8
    }
}

// round 17
// speedup vs baseline: 1.3847x; 1.0940x over previous
#include <cuda_runtime.h>
#include <cuda_bf16.h>
#include <math.h>

// Problem dims
#define BB 16
#define SS 100
#define LL 100          // MAX_CODE_LEN
#define FEAT 20         // INPUT_DIM
#define EMB 100
#define DD 320          // D = 20 + 3*100
#define RNNIN 340       // 2*20 + 3*100
#define HID 128
#define G4 512
#define NOUT 10

#define NVOC_N 10002
#define NVOC_P 50002
#define PROJ_NODE_BLOCKS 79   // ceil(10002/128)
#define PROJ_PATH_BLOCKS 391  // ceil(50002/128)
#define WS_STRIDE 68          // multiple of 4: float4 stays 16B-aligned
#define AS_STRIDE 104         // multiple of 4

// -------- scratch (device globals; no allocation allowed) --------
static __device__ __nv_bfloat16 g_Tn[NVOC_N * 640];  // bf16: [v][0:320]=start proj, [v][320:640]=end proj
static __device__ __nv_bfloat16 g_Tp[NVOC_P * 320];  // bf16 path proj
static __device__ float g_cw[BB*LL*SS];        // [b][l][s]
static __device__ float g_aw[BB*SS*LL];        // [b][s][l]
static __device__ float g_rnn[BB*SS*RNNIN];    // [b][s][340]
static __device__ float g_gx[BB*SS*G4];        // x-part gates
static __device__ float g_hs[BB*SS*HID];       // lstm outputs
static __device__ float g_WihT[RNNIN*G4];      // [k][n] coalesced
static __device__ uint4 g_Whh8[(HID/2)*HID];   // [kk][n]: bf16 gates (i,f,g,o) for k=2kk,2kk+1

__device__ __forceinline__ float sigf(float x) { return 1.0f / (1.0f + expf(-x)); }
__device__ __forceinline__ float tanh_fast(float x) {
    float y;
    asm("tanh.approx.f32 %0, %1;" : "=f"(y) : "f"(x));
    return y;
}
__device__ __forceinline__ float2 bf2f(unsigned u) {
    __nv_bfloat162 h = *reinterpret_cast<__nv_bfloat162*>(&u);
    return __bfloat1622float2(h);
}
__device__ __forceinline__ unsigned f2bf(float a, float b) {
    __nv_bfloat162 h = __float22bfloat162_rn(make_float2(a, b));
    return *reinterpret_cast<unsigned*>(&h);
}

// ----------------------------------------------------------------
// K0: transpose W_ih; pack W_hh as bf16 gate-quads for 2 k's per uint4
// ----------------------------------------------------------------
__global__ void k0_transpose(const float* __restrict__ Wih, const float* __restrict__ Whh) {
    int t = blockIdx.x * blockDim.x + threadIdx.x;
    if (t < RNNIN * G4) {          // Wih is [512][340]
        int n = t / RNNIN, k = t % RNNIN;
        g_WihT[k * G4 + n] = Wih[t];
    }
    if (t < (HID/2) * HID) {       // Whh is [512][128]: rows g*128+n, cols k
        int kk = t / HID, n = t % HID;
        int k0i = 2 * kk, k1i = 2 * kk + 1;
        uint4 w;
        w.x = f2bf(Whh[(0 * HID + n) * HID + k0i], Whh[(0 * HID + n) * HID + k1i]);
        w.y = f2bf(Whh[(1 * HID + n) * HID + k0i], Whh[(1 * HID + n) * HID + k1i]);
        w.z = f2bf(Whh[(2 * HID + n) * HID + k0i], Whh[(2 * HID + n) * HID + k1i]);
        w.w = f2bf(Whh[(3 * HID + n) * HID + k0i], Whh[(3 * HID + n) * HID + k1i]);
        g_Whh8[kk * HID + n] = w;
    }
}

// ----------------------------------------------------------------
// KP: project embedding tables through W_trans column blocks.
// Output stored as bf16 (tables L2-resident; k1b traffic halved).
// ----------------------------------------------------------------
__global__ void __launch_bounds__(256, 1)
kp_project(const float* __restrict__ etab_n,
           const float* __restrict__ etab_p,
           const float* __restrict__ Wt)
{
    extern __shared__ float sm[];
    float* A_s = sm;                        // 128 * 104
    float* W_s = sm + 128 * AS_STRIDE;      // 100 * 68

    const int t = threadIdx.x;
    const bool isnode = blockIdx.x < PROJ_NODE_BLOCKS;
    const int vb = isnode ? blockIdx.x : blockIdx.x - PROJ_NODE_BLOCKS;
    const int v0 = vb * 128;
    const int nv = isnode ? NVOC_N : NVOC_P;
    const float* tab = isnode ? etab_n : etab_p;
    __nv_bfloat16* outp = isnode ? g_Tn : g_Tp;
    const int ostride = isnode ? 640 : 320;
    const int ndb = isnode ? 10 : 5;

    for (int e = t; e < 128 * EMB; e += 256) {
        int r = e / EMB, k = e % EMB;
        float v = 0.f;
        if (v0 + r < nv) v = tab[(v0 + r) * EMB + k];
        A_s[r * AS_STRIDE + k] = v;
    }

    const int tx = t & 15;
    const int ty = t >> 4;
    const int d0 = tx * 4;
    const int r0 = ty * 8;

    for (int db = 0; db < ndb; db++) {
        const int dbase = db * 64;
        int wrow, kofs;
        if (isnode) {
            if (db < 5) { wrow = dbase;       kofs = 0;   }
            else        { wrow = dbase - 320; kofs = 100; }
        } else          { wrow = dbase;       kofs = 200; }

        __syncthreads();
        for (int e = t; e < 64 * EMB; e += 256) {
            int d = e / EMB, k = e % EMB;
            W_s[k * WS_STRIDE + d] = Wt[(wrow + d) * DD + kofs + k];
        }
        __syncthreads();

        float acc[8][4];
#pragma unroll
        for (int i = 0; i < 8; i++)
#pragma unroll
            for (int j = 0; j < 4; j++) acc[i][j] = 0.f;

#pragma unroll 2
        for (int k = 0; k < EMB; k += 4) {
            float4 wv0 = *(const float4*)&W_s[(k + 0) * WS_STRIDE + d0];
            float4 wv1 = *(const float4*)&W_s[(k + 1) * WS_STRIDE + d0];
            float4 wv2 = *(const float4*)&W_s[(k + 2) * WS_STRIDE + d0];
            float4 wv3 = *(const float4*)&W_s[(k + 3) * WS_STRIDE + d0];
#pragma unroll
            for (int i = 0; i < 8; i++) {
                float4 a = *(const float4*)&A_s[(r0 + i) * AS_STRIDE + k];
                acc[i][0] += a.x * wv0.x + a.y * wv1.x + a.z * wv2.x + a.w * wv3.x;
                acc[i][1] += a.x * wv0.y + a.y * wv1.y + a.z * wv2.y + a.w * wv3.y;
                acc[i][2] += a.x * wv0.z + a.y * wv1.z + a.z * wv2.z + a.w * wv3.z;
                acc[i][3] += a.x * wv0.w + a.y * wv1.w + a.z * wv2.w + a.w * wv3.w;
            }
        }
#pragma unroll
        for (int i = 0; i < 8; i++) {
            int r = v0 + r0 + i;
            if (r < nv) {
                uint2 o;
                o.x = f2bf(acc[i][0], acc[i][1]);
                o.y = f2bf(acc[i][2], acc[i][3]);
                *(uint2*)&outp[r * ostride + dbase + d0] = o;   // 8B-aligned (d0 mult of 4)
            }
        }
    }
}

// ----------------------------------------------------------------
// K1b: per (b,s): f_proj = feat @ Wt4^T + bt; per context l:
//   cw = ba + sum_d Wa[d]*tanh(Tn_s[si][d]+Tn_e[ei][d]+Tp[pi][d]+fproj[d])
// bf16 table gathers (uint4 = 8 elems); two contexts per warp.
// ----------------------------------------------------------------
__global__ void __launch_bounds__(256)
k1b_cw(const float* __restrict__ x,
       const float* __restrict__ Wt,
       const float* __restrict__ bt,
       const float* __restrict__ Wa,
       const float* __restrict__ ba)
{
    __shared__ int si[LL], pi[LL], ei[LL];
    __shared__ float4 fproj4[DD/4], was4[DD/4];
    __shared__ float feat_s[FEAT];
    float* fproj = (float*)fproj4;
    float* was   = (float*)was4;

    const int bs = blockIdx.x;
    const int b = bs / SS, s = bs % SS;
    const int t = threadIdx.x;

    if (t < LL) {
        int xb = bs * DD + FEAT + 3 * t;
        si[t] = (int)x[xb];
        pi[t] = (int)x[xb + 1];
        ei[t] = (int)x[xb + 2];
    }
    if (t < FEAT) feat_s[t] = x[bs * DD + t];
    __syncthreads();

    for (int d = t; d < DD; d += 256) {
        float acc = bt[d];
        const float* wrow = &Wt[d * DD + 300];
#pragma unroll
        for (int k = 0; k < FEAT; k++) acc += feat_s[k] * wrow[k];
        fproj[d] = acc;
        was[d] = Wa[d];
    }
    __syncthreads();

    const int warp = t >> 5, lane = t & 31;
    const float bav = ba[0];
    for (int l0 = warp; l0 < 50; l0 += 8) {
        const int l1 = l0 + 50;
        const uint4* pn0 = (const uint4*)&g_Tn[si[l0] * 640];
        const uint4* pe0 = (const uint4*)&g_Tn[ei[l0] * 640 + 320];
        const uint4* pp0 = (const uint4*)&g_Tp[pi[l0] * 320];
        const uint4* pn1 = (const uint4*)&g_Tn[si[l1] * 640];
        const uint4* pe1 = (const uint4*)&g_Tn[ei[l1] * 640 + 320];
        const uint4* pp1 = (const uint4*)&g_Tp[pi[l1] * 320];
        float sum0 = 0.f, sum1 = 0.f;
        // 40 chunks of 8 elems cover DD=320
        for (int j = lane; j < DD/8; j += 32) {
            float4 f0 = fproj4[2*j], f1 = fproj4[2*j+1];
            float4 w0 = was4[2*j],   w1 = was4[2*j+1];
            {
                uint4 an = pn0[j], ae = pe0[j], ap = pp0[j];
                float2 nA = bf2f(an.x), eA = bf2f(ae.x), pA = bf2f(ap.x);
                float2 nB = bf2f(an.y), eB = bf2f(ae.y), pB = bf2f(ap.y);
                float2 nC = bf2f(an.z), eC = bf2f(ae.z), pC = bf2f(ap.z);
                float2 nD = bf2f(an.w), eD = bf2f(ae.w), pD = bf2f(ap.w);
                sum0 += w0.x * tanh_fast(nA.x + eA.x + pA.x + f0.x)
                      + w0.y * tanh_fast(nA.y + eA.y + pA.y + f0.y)
                      + w0.z * tanh_fast(nB.x + eB.x + pB.x + f0.z)
                      + w0.w * tanh_fast(nB.y + eB.y + pB.y + f0.w)
                      + w1.x * tanh_fast(nC.x + eC.x + pC.x + f1.x)
                      + w1.y * tanh_fast(nC.y + eC.y + pC.y + f1.y)
                      + w1.z * tanh_fast(nD.x + eD.x + pD.x + f1.z)
                      + w1.w * tanh_fast(nD.y + eD.y + pD.y + f1.w);
            }
            {
                uint4 an = pn1[j], ae = pe1[j], ap = pp1[j];
                float2 nA = bf2f(an.x), eA = bf2f(ae.x), pA = bf2f(ap.x);
                float2 nB = bf2f(an.y), eB = bf2f(ae.y), pB = bf2f(ap.y);
                float2 nC = bf2f(an.z), eC = bf2f(ae.z), pC = bf2f(ap.z);
                float2 nD = bf2f(an.w), eD = bf2f(ae.w), pD = bf2f(ap.w);
                sum1 += w0.x * tanh_fast(nA.x + eA.x + pA.x + f0.x)
                      + w0.y * tanh_fast(nA.y + eA.y + pA.y + f0.y)
                      + w0.z * tanh_fast(nB.x + eB.x + pB.x + f0.z)
                      + w0.w * tanh_fast(nB.y + eB.y + pB.y + f0.w)
                      + w1.x * tanh_fast(nC.x + eC.x + pC.x + f1.x)
                      + w1.y * tanh_fast(nC.y + eC.y + pC.y + f1.y)
                      + w1.z * tanh_fast(nD.x + eD.x + pD.x + f1.z)
                      + w1.w * tanh_fast(nD.y + eD.y + pD.y + f1.w);
            }
        }
#pragma unroll
        for (int off = 16; off; off >>= 1) {
            sum0 += __shfl_xor_sync(~0u, sum0, off);
            sum1 += __shfl_xor_sync(~0u, sum1, off);
        }
        if (lane == 0) {
            g_cw[(b * LL + l0) * SS + s] = sum0 + bav;
            g_cw[(b * LL + l1) * SS + s] = sum1 + bav;
        }
    }
}

// ----------------------------------------------------------------
// K2: softmax over s (axis=1) for each (b,l); write aw in [b][s][l]
// ----------------------------------------------------------------
__global__ void k2_softmax() {
    const int bl = blockIdx.x;
    const int t  = threadIdx.x;    // 128
    const float* row = g_cw + bl * SS;
    float v0 = (t < SS) ? row[t] : -3.0e38f;

    __shared__ float sw[4];
    float v = v0;
#pragma unroll
    for (int off = 16; off; off >>= 1) v = fmaxf(v, __shfl_xor_sync(~0u, v, off));
    if ((t & 31) == 0) sw[t >> 5] = v;
    __syncthreads();
    float mx = fmaxf(fmaxf(sw[0], sw[1]), fmaxf(sw[2], sw[3]));
    __syncthreads();

    float e = (t < SS) ? expf(v0 - mx) : 0.f;
    float sv = e;
#pragma unroll
    for (int off = 16; off; off >>= 1) sv += __shfl_xor_sync(~0u, sv, off);
    if ((t & 31) == 0) sw[t >> 5] = sv;
    __syncthreads();
    float tot = sw[0] + sw[1] + sw[2] + sw[3];

    if (t < SS) {
        int b = bl / LL, l = bl % LL;
        g_aw[(b * SS + t) * LL + l] = e / tot;
    }
}

// ----------------------------------------------------------------
// K3: code_vec via re-gather (fp32 embedding tables — exact);
// rnn_in = [feat(20), code_vec(320)]
// ----------------------------------------------------------------
__global__ void k3_codevec(const float* __restrict__ x,
                           const float* __restrict__ etab_n,
                           const float* __restrict__ etab_p)
{
    __shared__ float aw_s[LL];
    __shared__ int si[LL], pi[LL], ei[LL];
    __shared__ float awsum_s;
    const int bs = blockIdx.x;
    const int t  = threadIdx.x;   // 128

    if (t < LL) {
        aw_s[t] = g_aw[bs * LL + t];
        int xb = bs * DD + FEAT + 3 * t;
        si[t] = (int)x[xb];
        pi[t] = (int)x[xb + 1];
        ei[t] = (int)x[xb + 2];
    }
    __syncthreads();
    if (t == 0) {
        float a = 0.f;
        for (int l = 0; l < LL; l++) a += aw_s[l];
        awsum_s = a;
    }
    __syncthreads();

    float* outrow = g_rnn + bs * RNNIN;
    for (int j = t; j < RNNIN; j += 128) {
        float v;
        if (j < FEAT) {
            v = x[bs * DD + j];
        } else {
            int k = j - FEAT;
            float acc = 0.f;
            if (k < EMB) {
                for (int l = 0; l < LL; l++) acc += etab_n[si[l] * EMB + k] * aw_s[l];
            } else if (k < 2 * EMB) {
                int km = k - EMB;
                for (int l = 0; l < LL; l++) acc += etab_n[ei[l] * EMB + km] * aw_s[l];
            } else if (k < 3 * EMB) {
                int km = k - 2 * EMB;
                for (int l = 0; l < LL; l++) acc += etab_p[pi[l] * EMB + km] * aw_s[l];
            } else {
                acc = x[bs * DD + (k - 3 * EMB)] * awsum_s;
            }
            v = acc;
        }
        outrow[j] = v;
    }
}

// ----------------------------------------------------------------
// K4: g_gx = rnn_in @ W_ih^T + b_ih + b_hh  (coalesced WihT scalar loads)
// ----------------------------------------------------------------
__global__ void __launch_bounds__(512)
k4_gates(const float* __restrict__ bih, const float* __restrict__ bhh)
{
    __shared__ float A_s[16 * RNNIN];
    const int n  = threadIdx.x;
    const int r0 = blockIdx.x * 16;

    for (int e = n; e < 16 * RNNIN; e += 512)
        A_s[e] = g_rnn[r0 * RNNIN + e];
    __syncthreads();

    float acc[16];
#pragma unroll
    for (int i = 0; i < 16; i++) acc[i] = 0.f;

#pragma unroll 2
    for (int k = 0; k < RNNIN; k += 4) {
        float w0 = g_WihT[(k + 0) * G4 + n];
        float w1 = g_WihT[(k + 1) * G4 + n];
        float w2 = g_WihT[(k + 2) * G4 + n];
        float w3 = g_WihT[(k + 3) * G4 + n];
#pragma unroll
        for (int i = 0; i < 16; i++) {
            float4 a = *(const float4*)&A_s[i * RNNIN + k];
            acc[i] += a.x * w0 + a.y * w1 + a.z * w2 + a.w * w3;
        }
    }
    float bias = bih[n] + bhh[n];
#pragma unroll
    for (int i = 0; i < 16; i++)
        g_gx[(r0 + i) * G4 + n] = acc[i] + bias;
}

// ----------------------------------------------------------------
// K5: LSTM recurrence, bf16-packed W_hh fully smem-resident (128 KB).
// Thread (q,n): gates of unit n over k in [32q,32q+32), 16 LDS.128/step.
// fp32 accumulation; only weights are bf16-rounded.
// ----------------------------------------------------------------
#define K5_SMEM ((HID/2)*HID*16 + 4*HID*16 + HID*4)

__global__ void __launch_bounds__(512)
k5_lstm()
{
    extern __shared__ uint4 smu[];
    uint4*  W_s = smu;                         // 64*128 uint4 = 128 KB
    float4* red = (float4*)(smu + (HID/2) * HID);   // 4*128 float4
    float*  h_s = (float*)(red + 4 * HID);

    const int b = blockIdx.x;
    const int n = threadIdx.x & 127;
    const int q = threadIdx.x >> 7;

    for (int e = threadIdx.x; e < (HID/2) * HID; e += 512)
        W_s[e] = g_Whh8[e];
    if (threadIdx.x < HID) h_s[threadIdx.x] = 0.f;
    float c = 0.f;
    __syncthreads();

    const uint4* wb = &W_s[q * 16 * HID + n];
    const float* hq = &h_s[q * 32];

    for (int s = 0; s < SS; s++) {
        float4 acc = make_float4(0.f, 0.f, 0.f, 0.f);
#pragma unroll 8
        for (int kk = 0; kk < 16; kk++) {
            uint4 w = wb[kk * HID];
            float h0 = hq[2 * kk], h1 = hq[2 * kk + 1];
            float2 wi = bf2f(w.x), wf = bf2f(w.y), wg = bf2f(w.z), wo = bf2f(w.w);
            acc.x += wi.x * h0 + wi.y * h1;
            acc.y += wf.x * h0 + wf.y * h1;
            acc.z += wg.x * h0 + wg.y * h1;
            acc.w += wo.x * h0 + wo.y * h1;
        }
        red[q * HID + n] = acc;
        __syncthreads();
        if (threadIdx.x < HID) {
            float4 a0 = red[0 * HID + threadIdx.x];
            float4 a1 = red[1 * HID + threadIdx.x];
            float4 a2 = red[2 * HID + threadIdx.x];
            float4 a3 = red[3 * HID + threadIdx.x];
            const float* gx = &g_gx[(b * SS + s) * G4];
            float gi = a0.x + a1.x + a2.x + a3.x + gx[threadIdx.x];
            float gf = a0.y + a1.y + a2.y + a3.y + gx[HID + threadIdx.x];
            float gg = a0.z + a1.z + a2.z + a3.z + gx[2 * HID + threadIdx.x];
            float go = a0.w + a1.w + a2.w + a3.w + gx[3 * HID + threadIdx.x];
            c = sigf(gf) * c + sigf(gi) * tanhf(gg);
            float h = sigf(go) * tanhf(c);
            h_s[threadIdx.x] = h;
            g_hs[(b * SS + s) * HID + threadIdx.x] = h;
        }
        __syncthreads();
    }
}

// ----------------------------------------------------------------
// K6: out = sigmoid(hs @ W_fc^T + b_fc)
// ----------------------------------------------------------------
__global__ void k6_fc(const float* __restrict__ Wfc,
                      const float* __restrict__ bfc,
                      float* __restrict__ out)
{
    int t = blockIdx.x * blockDim.x + threadIdx.x;
    if (t >= BB * SS * NOUT) return;
    int bs = t / NOUT;
    int o  = t % NOUT;
    const float* hrow = g_hs + bs * HID;
    const float* wrow = Wfc + o * HID;
    float acc = bfc[o];
#pragma unroll 8
    for (int u = 0; u < HID; u++) acc += hrow[u] * wrow[u];
    out[t] = sigf(acc);
}

// ----------------------------------------------------------------
extern "C" void kernel_launch(void* const* d_in, const int* in_sizes, int n_in,
                              void* d_out, int out_size)
{
    const float* x      = (const float*)d_in[0];
    const float* etab_n = (const float*)d_in[1];
    const float* etab_p = (const float*)d_in[2];
    const float* Wt     = (const float*)d_in[3];
    const float* bt     = (const float*)d_in[4];
    const float* Wa     = (const float*)d_in[5];
    const float* ba     = (const float*)d_in[6];
    const float* Wih    = (const float*)d_in[7];
    const float* Whh    = (const float*)d_in[8];
    const float* bih    = (const float*)d_in[9];
    const float* bhh    = (const float*)d_in[10];
    const float* Wfc    = (const float*)d_in[11];
    const float* bfc    = (const float*)d_in[12];
    float* out = (float*)d_out;

    const int kp_smem = (128 * AS_STRIDE + 100 * WS_STRIDE) * 4;
    cudaFuncSetAttribute(kp_project, cudaFuncAttributeMaxDynamicSharedMemorySize, kp_smem);
    cudaFuncSetAttribute(k5_lstm, cudaFuncAttributeMaxDynamicSharedMemorySize, K5_SMEM);

    {
        int total = RNNIN * G4;
        k0_transpose<<<(total + 255) / 256, 256>>>(Wih, Whh);     // 1
    }
    kp_project<<<PROJ_NODE_BLOCKS + PROJ_PATH_BLOCKS, 256, kp_smem>>>(etab_n, etab_p, Wt); // 2
    k1b_cw<<<BB * SS, 256>>>(x, Wt, bt, Wa, ba);                  // 3
    k2_softmax<<<BB * LL, 128>>>();                               // 4
    k3_codevec<<<BB * SS, 128>>>(x, etab_n, etab_p);              // 5
    k4_gates<<<BB * SS / 16, 512>>>(bih, bhh);                    // 6
    k5_lstm<<<BB, 512, K5_SMEM>>>();                              // 7
    {
        int total = BB * SS * NOUT;
        k6_fc<<<(total + 255) / 256, 256>>>(Wfc, bfc, out);       // 8
    }
}